// round 1
// baseline (speedup 1.0000x reference)
#include <cuda_runtime.h>
#include <cstdint>

#define E_EDGES 320000
#define N_NODES 20000
#define F_DIM   128
#define N_RBF   20
#define TILE_E  64
#define THREADS 256
#define NTILES  (E_EDGES / TILE_E)   // 5000 exactly

// out layout assumption: out_v (N,3,F) at offset 0, out_s (N,F) after it.
#define OUT_S_OFF (N_NODES * 3 * F_DIM)

typedef unsigned long long ull;

__device__ double g_sumsq;

__device__ __forceinline__ ull pack2(float lo, float hi) {
    ull r; asm("mov.b64 %0, {%1,%2};" : "=l"(r) : "f"(lo), "f"(hi)); return r;
}
__device__ __forceinline__ float2 unpack2(ull v) {
    float2 f; asm("mov.b64 {%0,%1}, %2;" : "=f"(f.x), "=f"(f.y) : "l"(v)); return f;
}
__device__ __forceinline__ void ffma2(ull& d, ull a, ull b) {
    asm("fma.rn.f32x2 %0, %1, %2, %0;" : "+l"(d) : "l"(a), "l"(b));
}
__device__ __forceinline__ ull mul2(ull a, ull b) {
    ull d; asm("mul.rn.f32x2 %0, %1, %2;" : "=l"(d) : "l"(a), "l"(b)); return d;
}
__device__ __forceinline__ void red4(float* p, float a, float b, float c, float d) {
    asm volatile("red.global.add.v4.f32 [%0], {%1,%2,%3,%4};"
                 :: "l"(p), "f"(a), "f"(b), "f"(c), "f"(d) : "memory");
}

__global__ void zero_kernel(float4* __restrict__ out, int n4) {
    int i = blockIdx.x * blockDim.x + threadIdx.x;
    if (i == 0) g_sumsq = 0.0;
    int stride = gridDim.x * blockDim.x;
    for (; i < n4; i += stride) out[i] = make_float4(0.f, 0.f, 0.f, 0.f);
}

__global__ void sumsq_kernel(const float* __restrict__ r, int n) {
    float s = 0.f;
    for (int i = blockIdx.x * blockDim.x + threadIdx.x; i < n;
         i += gridDim.x * blockDim.x) {
        float x = r[i];
        s += x * x;
    }
    #pragma unroll
    for (int o = 16; o > 0; o >>= 1) s += __shfl_down_sync(0xffffffffu, s, o);
    __shared__ float ws[8];
    if ((threadIdx.x & 31) == 0) ws[threadIdx.x >> 5] = s;
    __syncthreads();
    if (threadIdx.x < 8) {
        float t = ws[threadIdx.x];
        #pragma unroll
        for (int o = 4; o > 0; o >>= 1) t += __shfl_down_sync(0xffu, t, o);
        if (threadIdx.x == 0) atomicAdd(&g_sumsq, (double)t);
    }
}

// grid: (blocks_x, 3). blockIdx.y = column group (0: sp0*v, 1: out_s, 2: dir term)
__global__ void __launch_bounds__(THREADS, 2)
main_kernel(const float* __restrict__ s, const float* __restrict__ r,
            const float* __restrict__ v, const int* __restrict__ idx,
            const float* __restrict__ Wphi, const float* __restrict__ bphi,
            const float* __restrict__ Ww, const float* __restrict__ bw,
            float* __restrict__ out)
{
    extern __shared__ float sm[];
    float* W_s    = sm;                      // 128*128
    float* Ww_s   = W_s + 128 * 128;         // 20*128
    float* bphi_s = Ww_s + 20 * 128;         // 128
    float* bw_s   = bphi_s + 128;            // 128
    float* s_tile = bw_s + 128;              // 64*128
    float* rbf_s  = s_tile + 64 * 128;       // 64*20
    float* r_s    = rbf_s + 64 * 20;         // 64*3
    int*   idx_s  = (int*)(r_s + 64 * 3);    // 64

    const int tid   = threadIdx.x;
    const int group = blockIdx.y;
    const int goff  = group * 128;
    const int tc    = tid & 15;     // 16 column-threads, 8 cols each
    const int te    = tid >> 4;     // 16 edge-threads, 4 edges each
    const int gl    = tc * 8;

    // Load weight slices for this column group (reused across all tiles)
    for (int i = tid; i < 128 * 32; i += THREADS) {
        int f = i >> 5, c4 = i & 31;
        *(float4*)&W_s[f * 128 + c4 * 4] =
            *(const float4*)&Wphi[f * 384 + goff + c4 * 4];
    }
    for (int i = tid; i < 20 * 32; i += THREADS) {
        int n = i >> 5, c4 = i & 31;
        *(float4*)&Ww_s[n * 128 + c4 * 4] =
            *(const float4*)&Ww[n * 384 + goff + c4 * 4];
    }
    if (tid < 128) {
        bphi_s[tid] = bphi[goff + tid];
        bw_s[tid]   = bw[goff + tid];
    }
    float ginv = 0.f;
    if (group == 2) ginv = (float)(1.0 / sqrt(g_sumsq));
    __syncthreads();

    for (int tile = blockIdx.x; tile < NTILES; tile += gridDim.x) {
        __syncthreads();  // prior iter done with staging buffers
        const int ebase = tile * TILE_E;

        for (int i = tid; i < 2048; i += THREADS)   // 64*128 floats as float4
            *(float4*)&s_tile[i * 4] = *(const float4*)&s[ebase * 128 + i * 4];
        if (tid < 64)  idx_s[tid] = idx[ebase + tid];
        if (tid < 192) r_s[tid]   = r[ebase * 3 + tid];
        __syncthreads();

        // RBF per (edge, n): exact replica of reference (cutoff applied to rbf value)
        for (int i = tid; i < TILE_E * N_RBF; i += THREADS) {
            int el = i / N_RBF, n = i - el * N_RBF;
            float rx = r_s[el * 3], ry = r_s[el * 3 + 1], rz = r_s[el * 3 + 2];
            float rn = sqrtf(rx * rx + ry * ry + rz * rz);
            float t  = sinf((float)(n + 1) * (3.14159265358979323846f / 5.0f) * rn) / rn;
            rbf_s[i] = (t <= 5.0f)
                       ? 0.5f * (cosf(3.14159265358979323846f * 0.2f * t) + 1.0f)
                       : 0.0f;
        }
        __syncthreads();

        // ---- GEMM: phi[4 edges][8 cols] via fma.rn.f32x2 ----
        ull acc[4][4];
        {
            float4 b0 = *(float4*)&bphi_s[gl];
            float4 b1 = *(float4*)&bphi_s[gl + 4];
            #pragma unroll
            for (int i = 0; i < 4; i++) {
                acc[i][0] = pack2(b0.x, b0.y); acc[i][1] = pack2(b0.z, b0.w);
                acc[i][2] = pack2(b1.x, b1.y); acc[i][3] = pack2(b1.z, b1.w);
            }
        }
        #pragma unroll 1
        for (int fo = 0; fo < 128; fo += 4) {
            float4 sv[4];
            #pragma unroll
            for (int i = 0; i < 4; i++)
                sv[i] = *(float4*)&s_tile[(te * 4 + i) * 128 + fo];
            #pragma unroll
            for (int k = 0; k < 4; k++) {
                float4 w0 = *(float4*)&W_s[(fo + k) * 128 + gl];
                float4 w1 = *(float4*)&W_s[(fo + k) * 128 + gl + 4];
                ull b0 = pack2(w0.x, w0.y), b1 = pack2(w0.z, w0.w);
                ull b2 = pack2(w1.x, w1.y), b3 = pack2(w1.z, w1.w);
                #pragma unroll
                for (int i = 0; i < 4; i++) {
                    float sk = (k == 0) ? sv[i].x : (k == 1) ? sv[i].y
                             : (k == 2) ? sv[i].z : sv[i].w;
                    ull a = pack2(sk, sk);
                    ffma2(acc[i][0], a, b0); ffma2(acc[i][1], a, b1);
                    ffma2(acc[i][2], a, b2); ffma2(acc[i][3], a, b3);
                }
            }
        }

        // ---- epilogue: w = rbf @ Ww + bw ; split = w*phi ; scatter ----
        #pragma unroll 1
        for (int i = 0; i < 4; i++) {
            const int el = te * 4 + i;
            const int eg = ebase + el;
            const int node = idx_s[el];

            float4 bw0 = *(float4*)&bw_s[gl], bw1 = *(float4*)&bw_s[gl + 4];
            ull w0 = pack2(bw0.x, bw0.y), w1 = pack2(bw0.z, bw0.w);
            ull w2 = pack2(bw1.x, bw1.y), w3 = pack2(bw1.z, bw1.w);
            #pragma unroll
            for (int n = 0; n < N_RBF; n++) {
                float rb = rbf_s[el * N_RBF + n];
                ull a = pack2(rb, rb);
                float4 q0 = *(float4*)&Ww_s[n * 128 + gl];
                float4 q1 = *(float4*)&Ww_s[n * 128 + gl + 4];
                ffma2(w0, a, pack2(q0.x, q0.y)); ffma2(w1, a, pack2(q0.z, q0.w));
                ffma2(w2, a, pack2(q1.x, q1.y)); ffma2(w3, a, pack2(q1.z, q1.w));
            }
            float2 f0 = unpack2(mul2(w0, acc[i][0]));
            float2 f1 = unpack2(mul2(w1, acc[i][1]));
            float2 f2 = unpack2(mul2(w2, acc[i][2]));
            float2 f3 = unpack2(mul2(w3, acc[i][3]));
            float sp[8] = {f0.x, f0.y, f1.x, f1.y, f2.x, f2.y, f3.x, f3.y};

            if (group == 0) {
                #pragma unroll
                for (int d = 0; d < 3; d++) {
                    float4 vv0 = __ldg((const float4*)&v[(eg * 3 + d) * 128 + gl]);
                    float4 vv1 = __ldg((const float4*)&v[(eg * 3 + d) * 128 + gl + 4]);
                    float* dst = &out[(node * 3 + d) * 128 + gl];
                    red4(dst,     sp[0] * vv0.x, sp[1] * vv0.y, sp[2] * vv0.z, sp[3] * vv0.w);
                    red4(dst + 4, sp[4] * vv1.x, sp[5] * vv1.y, sp[6] * vv1.z, sp[7] * vv1.w);
                }
            } else if (group == 1) {
                float* dst = &out[OUT_S_OFF + node * 128 + gl];
                red4(dst,     sp[0], sp[1], sp[2], sp[3]);
                red4(dst + 4, sp[4], sp[5], sp[6], sp[7]);
            } else {
                #pragma unroll
                for (int d = 0; d < 3; d++) {
                    float c = r_s[el * 3 + d] * ginv;
                    float* dst = &out[(node * 3 + d) * 128 + gl];
                    red4(dst,     sp[0] * c, sp[1] * c, sp[2] * c, sp[3] * c);
                    red4(dst + 4, sp[4] * c, sp[5] * c, sp[6] * c, sp[7] * c);
                }
            }
        }
    }
}

extern "C" void kernel_launch(void* const* d_in, const int* in_sizes, int n_in,
                              void* d_out, int out_size) {
    const float* s    = (const float*)d_in[0];
    const float* r    = (const float*)d_in[1];
    const float* v    = (const float*)d_in[2];
    const int*   idx  = (const int*)d_in[3];
    const float* Wphi = (const float*)d_in[4];
    const float* bphi = (const float*)d_in[5];
    const float* Ww   = (const float*)d_in[6];
    const float* bw   = (const float*)d_in[7];
    float* out = (float*)d_out;

    zero_kernel<<<2048, THREADS>>>((float4*)out, out_size / 4);
    sumsq_kernel<<<256, THREADS>>>(r, E_EDGES * 3);

    size_t smem = (size_t)(128 * 128 + 20 * 128 + 128 + 128 +
                           64 * 128 + 64 * 20 + 64 * 3 + 64) * 4;
    cudaFuncSetAttribute(main_kernel,
                         cudaFuncAttributeMaxDynamicSharedMemorySize, (int)smem);
    main_kernel<<<dim3(512, 3), THREADS, smem>>>(s, r, v, idx, Wphi, bphi,
                                                 Ww, bw, out);
}

// round 2
// speedup vs baseline: 1.2317x; 1.2317x over previous
#include <cuda_runtime.h>
#include <cstdint>
#include <cstddef>

#define E_EDGES 320000
#define N_NODES 20000
#define F_DIM   128
#define N_RBF   20
#define TILE_E  128
#define NTILES  (E_EDGES / TILE_E)   // 2500 exactly

#define OUT_S_OFF ((size_t)N_NODES * 3 * F_DIM)

typedef unsigned long long ull;

// ---- device scratch (no runtime allocation allowed) ----
__device__ float  g_msg[(size_t)E_EDGES * 384];   // per-edge sp0|sp1|sp2
__device__ int    g_hist[N_NODES];
__device__ int    g_cursor[N_NODES];
__device__ int    g_off[N_NODES + 1];
__device__ int    g_elist[E_EDGES];
__device__ double g_sumsq;

__device__ __forceinline__ ull pack2(float lo, float hi) {
    ull r; asm("mov.b64 %0, {%1,%2};" : "=l"(r) : "f"(lo), "f"(hi)); return r;
}
__device__ __forceinline__ float2 unpack2(ull v) {
    float2 f; asm("mov.b64 {%0,%1}, %2;" : "=f"(f.x), "=f"(f.y) : "l"(v)); return f;
}
__device__ __forceinline__ void ffma2(ull& d, ull a, ull b) {
    asm("fma.rn.f32x2 %0, %1, %2, %0;" : "+l"(d) : "l"(a), "l"(b));
}
__device__ __forceinline__ ull mul2(ull a, ull b) {
    ull d; asm("mul.rn.f32x2 %0, %1, %2;" : "=l"(d) : "l"(a), "l"(b)); return d;
}

// ---- K0: reset counters + sumsq ----
__global__ void reset_kernel() {
    int i = blockIdx.x * blockDim.x + threadIdx.x;
    if (i == 0) g_sumsq = 0.0;
    int stride = gridDim.x * blockDim.x;
    for (int j = i; j < N_NODES; j += stride) { g_hist[j] = 0; g_cursor[j] = 0; }
}

// ---- K1: histogram + global sum of squares of r ----
__global__ void hist_sumsq_kernel(const int* __restrict__ idx,
                                  const float* __restrict__ r) {
    int i = blockIdx.x * blockDim.x + threadIdx.x;
    int stride = gridDim.x * blockDim.x;
    for (int e = i; e < E_EDGES; e += stride)
        atomicAdd(&g_hist[idx[e]], 1);

    float s = 0.f;
    for (int j = i; j < E_EDGES * 3; j += stride) { float x = r[j]; s += x * x; }
    #pragma unroll
    for (int o = 16; o > 0; o >>= 1) s += __shfl_down_sync(0xffffffffu, s, o);
    __shared__ float ws[8];
    if ((threadIdx.x & 31) == 0) ws[threadIdx.x >> 5] = s;
    __syncthreads();
    if (threadIdx.x < 8) {
        float t = ws[threadIdx.x];
        #pragma unroll
        for (int o = 4; o > 0; o >>= 1) t += __shfl_down_sync(0xffu, t, o);
        if (threadIdx.x == 0) atomicAdd(&g_sumsq, (double)t);
    }
}

// ---- K2: exclusive scan of hist -> off (single block) ----
__global__ void scan_kernel() {
    const int CH = 79;               // 256*79 = 20224 >= 20000
    __shared__ int part[256];
    int t = threadIdx.x;
    int base = t * CH;
    int s = 0;
    for (int i = 0; i < CH; i++) { int j = base + i; if (j < N_NODES) s += g_hist[j]; }
    part[t] = s;
    __syncthreads();
    for (int o = 1; o < 256; o <<= 1) {
        int v = (t >= o) ? part[t - o] : 0;
        __syncthreads();
        part[t] += v;
        __syncthreads();
    }
    int run = (t > 0) ? part[t - 1] : 0;
    for (int i = 0; i < CH; i++) {
        int j = base + i;
        if (j < N_NODES) { g_off[j] = run; run += g_hist[j]; }
    }
    if (t == 255) g_off[N_NODES] = run;
}

// ---- K3: fill CSR edge list ----
__global__ void fill_kernel(const int* __restrict__ idx) {
    int i = blockIdx.x * blockDim.x + threadIdx.x;
    int stride = gridDim.x * blockDim.x;
    for (int e = i; e < E_EDGES; e += stride) {
        int n = idx[e];
        int pos = g_off[n] + atomicAdd(&g_cursor[n], 1);
        g_elist[pos] = e;
    }
}

// ---- K4: fused GEMM -> per-edge sp messages (no atomics, no v) ----
// grid (X, 3): blockIdx.y = column group g, cols [g*128, g*128+128)
__global__ void __launch_bounds__(512)
gemm_kernel(const float* __restrict__ s, const float* __restrict__ r,
            const float* __restrict__ Wphi, const float* __restrict__ bphi,
            const float* __restrict__ Ww, const float* __restrict__ bw)
{
    extern __shared__ float sm[];
    float* W_s    = sm;                       // 128*128 = 16384
    float* Ww_s   = W_s + 128 * 128;          // 20*128  = 2560
    float* s_tile = Ww_s + 20 * 128;          // 128*128 = 16384
    float* rbf_s  = s_tile + 128 * 128;       // 128*20  = 2560
    float* r_s    = rbf_s + 128 * 20;         // 128*3   = 384

    const int tid   = threadIdx.x;
    const int group = blockIdx.y;
    const int goff  = group * 128;
    const int tc    = tid & 15;      // 16 column-threads, 8 cols each
    const int teg   = tid >> 4;      // 32 edge-threads, 4 edges each
    const int gl    = tc * 8;

    for (int i = tid; i < 128 * 32; i += 512) {
        int f = i >> 5, c4 = i & 31;
        *(float4*)&W_s[f * 128 + c4 * 4] =
            *(const float4*)&Wphi[f * 384 + goff + c4 * 4];
    }
    for (int i = tid; i < 20 * 32; i += 512) {
        int n = i >> 5, c4 = i & 31;
        *(float4*)&Ww_s[n * 128 + c4 * 4] =
            *(const float4*)&Ww[n * 384 + goff + c4 * 4];
    }
    const float4 bp0 = *(const float4*)&bphi[goff + gl];
    const float4 bp1 = *(const float4*)&bphi[goff + gl + 4];
    const float4 bw0 = *(const float4*)&bw[goff + gl];
    const float4 bw1 = *(const float4*)&bw[goff + gl + 4];
    __syncthreads();

    for (int tile = blockIdx.x; tile < NTILES; tile += gridDim.x) {
        const int ebase = tile * TILE_E;

        for (int i = tid; i < 4096; i += 512)          // 128*128 floats
            *(float4*)&s_tile[i * 4] = *(const float4*)&s[(size_t)ebase * 128 + i * 4];
        if (tid < 384) r_s[tid] = r[ebase * 3 + tid];
        __syncthreads();

        for (int i = tid; i < TILE_E * N_RBF; i += 512) {
            int el = i / N_RBF, n = i - el * N_RBF;
            float rx = r_s[el * 3], ry = r_s[el * 3 + 1], rz = r_s[el * 3 + 2];
            float rn = sqrtf(rx * rx + ry * ry + rz * rz);
            float t  = sinf((float)(n + 1) * (3.14159265358979323846f / 5.0f) * rn) / rn;
            rbf_s[i] = (t <= 5.0f)
                       ? 0.5f * (cosf(3.14159265358979323846f * 0.2f * t) + 1.0f)
                       : 0.0f;
        }
        __syncthreads();

        // ---- w = rbf @ Ww + bw  (K=20, n-outer so Ww row is reused x4 edges)
        ull w[4][4];
        #pragma unroll
        for (int i = 0; i < 4; i++) {
            w[i][0] = pack2(bw0.x, bw0.y); w[i][1] = pack2(bw0.z, bw0.w);
            w[i][2] = pack2(bw1.x, bw1.y); w[i][3] = pack2(bw1.z, bw1.w);
        }
        #pragma unroll 1
        for (int n = 0; n < N_RBF; n++) {
            float4 q0 = *(float4*)&Ww_s[n * 128 + gl];
            float4 q1 = *(float4*)&Ww_s[n * 128 + gl + 4];
            ull b0 = pack2(q0.x, q0.y), b1 = pack2(q0.z, q0.w);
            ull b2 = pack2(q1.x, q1.y), b3 = pack2(q1.z, q1.w);
            #pragma unroll
            for (int i = 0; i < 4; i++) {
                float rb = rbf_s[(teg * 4 + i) * N_RBF + n];
                ull a = pack2(rb, rb);
                ffma2(w[i][0], a, b0); ffma2(w[i][1], a, b1);
                ffma2(w[i][2], a, b2); ffma2(w[i][3], a, b3);
            }
        }

        // ---- phi = s @ Wphi + bphi  (K=128)
        ull acc[4][4];
        #pragma unroll
        for (int i = 0; i < 4; i++) {
            acc[i][0] = pack2(bp0.x, bp0.y); acc[i][1] = pack2(bp0.z, bp0.w);
            acc[i][2] = pack2(bp1.x, bp1.y); acc[i][3] = pack2(bp1.z, bp1.w);
        }
        #pragma unroll 1
        for (int fo = 0; fo < 128; fo += 4) {
            float4 sv[4];
            #pragma unroll
            for (int i = 0; i < 4; i++)
                sv[i] = *(float4*)&s_tile[(teg * 4 + i) * 128 + fo];
            #pragma unroll
            for (int k = 0; k < 4; k++) {
                float4 w0 = *(float4*)&W_s[(fo + k) * 128 + gl];
                float4 w1 = *(float4*)&W_s[(fo + k) * 128 + gl + 4];
                ull b0 = pack2(w0.x, w0.y), b1 = pack2(w0.z, w0.w);
                ull b2 = pack2(w1.x, w1.y), b3 = pack2(w1.z, w1.w);
                #pragma unroll
                for (int i = 0; i < 4; i++) {
                    float sk = (k == 0) ? sv[i].x : (k == 1) ? sv[i].y
                             : (k == 2) ? sv[i].z : sv[i].w;
                    ull a = pack2(sk, sk);
                    ffma2(acc[i][0], a, b0); ffma2(acc[i][1], a, b1);
                    ffma2(acc[i][2], a, b2); ffma2(acc[i][3], a, b3);
                }
            }
        }

        // ---- sp = w * phi -> plain coalesced stores to g_msg
        #pragma unroll
        for (int i = 0; i < 4; i++) {
            const int eg = ebase + teg * 4 + i;
            float2 f0 = unpack2(mul2(w[i][0], acc[i][0]));
            float2 f1 = unpack2(mul2(w[i][1], acc[i][1]));
            float2 f2 = unpack2(mul2(w[i][2], acc[i][2]));
            float2 f3 = unpack2(mul2(w[i][3], acc[i][3]));
            float* dst = &g_msg[(size_t)eg * 384 + goff + gl];
            *(float4*)dst       = make_float4(f0.x, f0.y, f1.x, f1.y);
            *(float4*)(dst + 4) = make_float4(f2.x, f2.y, f3.x, f3.y);
        }
        __syncthreads();   // done with staging buffers before next iter
    }
}

// ---- K5: per-node gather (plain writes, covers every output element) ----
__global__ void __launch_bounds__(128)
gather_kernel(const float* __restrict__ r, const float* __restrict__ v,
              float* __restrict__ out)
{
    const int n = blockIdx.x;
    const int f = threadIdx.x;
    const float ginv = (float)(1.0 / sqrt(g_sumsq));
    const int beg = g_off[n], end = g_off[n + 1];

    float a0 = 0.f, a1 = 0.f, a2 = 0.f, as = 0.f;
    for (int p = beg; p < end; p++) {
        const int e = g_elist[p];
        const float* m  = &g_msg[(size_t)e * 384];
        const float* vp = &v[(size_t)e * 384];
        float sp0 = m[f], sp1 = m[128 + f], sp2 = m[256 + f];
        float r0 = __ldg(&r[e * 3]), r1 = __ldg(&r[e * 3 + 1]), r2 = __ldg(&r[e * 3 + 2]);
        a0 += sp2 * (r0 * ginv) + sp0 * vp[f];
        a1 += sp2 * (r1 * ginv) + sp0 * vp[128 + f];
        a2 += sp2 * (r2 * ginv) + sp0 * vp[256 + f];
        as += sp1;
    }
    size_t ob = (size_t)n * 384;
    out[ob + f]       = a0;
    out[ob + 128 + f] = a1;
    out[ob + 256 + f] = a2;
    out[OUT_S_OFF + (size_t)n * 128 + f] = as;
}

extern "C" void kernel_launch(void* const* d_in, const int* in_sizes, int n_in,
                              void* d_out, int out_size) {
    const float* s    = (const float*)d_in[0];
    const float* r    = (const float*)d_in[1];
    const float* v    = (const float*)d_in[2];
    const int*   idx  = (const int*)d_in[3];
    const float* Wphi = (const float*)d_in[4];
    const float* bphi = (const float*)d_in[5];
    const float* Ww   = (const float*)d_in[6];
    const float* bw   = (const float*)d_in[7];
    float* out = (float*)d_out;

    reset_kernel<<<64, 256>>>();
    hist_sumsq_kernel<<<256, 256>>>(idx, r);
    scan_kernel<<<1, 256>>>();
    fill_kernel<<<256, 256>>>(idx);

    size_t smem = (size_t)(128 * 128 + 20 * 128 + 128 * 128 + 128 * 20 + 128 * 3) * 4;
    cudaFuncSetAttribute(gemm_kernel,
                         cudaFuncAttributeMaxDynamicSharedMemorySize, (int)smem);
    gemm_kernel<<<dim3(250, 3), 512, smem>>>(s, r, Wphi, bphi, Ww, bw);

    gather_kernel<<<N_NODES, 128>>>(r, v, out);
}

// round 4
// speedup vs baseline: 1.9634x; 1.5941x over previous
#include <cuda_runtime.h>
#include <cuda_bf16.h>
#include <cstdint>
#include <cstddef>

#define E_EDGES 320000
#define N_NODES 20000
#define N_RBF   20
#define TILE_E  128
#define NTILES  2500
#define OUT_S_OFF ((size_t)N_NODES * 3 * 128)
#define PITCH   136          // bf16 elements per row (padded: conflict-free frags)

typedef unsigned long long ull;

// ---- device scratch ----
__device__ float  g_msg[(size_t)E_EDGES * 384];
__device__ int    g_hist[N_NODES];
__device__ int    g_cursor[N_NODES];
__device__ int    g_off[N_NODES + 1];
__device__ int    g_elist[E_EDGES];
__device__ double g_sumsq;

// ---- f32x2 helpers ----
__device__ __forceinline__ ull pack2(float lo, float hi) {
    ull r; asm("mov.b64 %0, {%1,%2};" : "=l"(r) : "f"(lo), "f"(hi)); return r;
}
__device__ __forceinline__ float2 unpack2(ull v) {
    float2 f; asm("mov.b64 {%0,%1}, %2;" : "=f"(f.x), "=f"(f.y) : "l"(v)); return f;
}
__device__ __forceinline__ void ffma2(ull& d, ull a, ull b) {
    asm("fma.rn.f32x2 %0, %1, %2, %0;" : "+l"(d) : "l"(a), "l"(b));
}
__device__ __forceinline__ ull mul2(ull a, ull b) {
    ull d; asm("mul.rn.f32x2 %0, %1, %2;" : "=l"(d) : "l"(a), "l"(b)); return d;
}
__device__ __forceinline__ ull add2(ull a, ull b) {
    ull d; asm("add.rn.f32x2 %0, %1, %2;" : "=l"(d) : "l"(a), "l"(b)); return d;
}

// ---- mma.sync m16n8k16 bf16 (baseline PTX, compiles under compute_103) ----
__device__ __forceinline__ void mma_bf16(float* d, uint32_t a0, uint32_t a1,
                                         uint32_t a2, uint32_t a3,
                                         uint32_t b0, uint32_t b1) {
    asm volatile(
        "mma.sync.aligned.m16n8k16.row.col.f32.bf16.bf16.f32 "
        "{%0,%1,%2,%3}, {%4,%5,%6,%7}, {%8,%9}, {%0,%1,%2,%3};"
        : "+f"(d[0]), "+f"(d[1]), "+f"(d[2]), "+f"(d[3])
        : "r"(a0), "r"(a1), "r"(a2), "r"(a3), "r"(b0), "r"(b1));
}

__device__ __forceinline__ void split2(float x0, float x1, uint32_t& hi, uint32_t& lo) {
    __nv_bfloat162 h = __floats2bfloat162_rn(x0, x1);
    float h0 = __low2float(h), h1 = __high2float(h);
    __nv_bfloat162 l = __floats2bfloat162_rn(x0 - h0, x1 - h1);
    hi = *reinterpret_cast<uint32_t*>(&h);
    lo = *reinterpret_cast<uint32_t*>(&l);
}

// smem byte offsets
#define OFF_AHI 0
#define OFF_ALO 34816
#define OFF_BHI 69632
#define OFF_BLO 104448
#define OFF_WW  139264           // fp32 20*128
#define OFF_BPHI 149504
#define OFF_BW   150016
#define OFF_RBF  150528          // fp32 128*21
#define SMEM_SZ  161280
// sp transpose buffer aliases A region: float[128][132] = 67584 B <= 69632

// ---- small CSR/misc kernels ----
__global__ void reset_kernel() {
    int i = blockIdx.x * blockDim.x + threadIdx.x;
    if (i == 0) g_sumsq = 0.0;
    int st = gridDim.x * blockDim.x;
    for (int j = i; j < N_NODES; j += st) { g_hist[j] = 0; g_cursor[j] = 0; }
}
__global__ void hist_sumsq_kernel(const int* __restrict__ idx,
                                  const float* __restrict__ r) {
    int i = blockIdx.x * blockDim.x + threadIdx.x;
    int st = gridDim.x * blockDim.x;
    for (int e = i; e < E_EDGES; e += st) atomicAdd(&g_hist[idx[e]], 1);
    float s = 0.f;
    for (int j = i; j < E_EDGES * 3; j += st) { float x = r[j]; s += x * x; }
    #pragma unroll
    for (int o = 16; o > 0; o >>= 1) s += __shfl_down_sync(0xffffffffu, s, o);
    __shared__ float ws[8];
    if ((threadIdx.x & 31) == 0) ws[threadIdx.x >> 5] = s;
    __syncthreads();
    if (threadIdx.x < 8) {
        float t = ws[threadIdx.x];
        #pragma unroll
        for (int o = 4; o > 0; o >>= 1) t += __shfl_down_sync(0xffu, t, o);
        if (threadIdx.x == 0) atomicAdd(&g_sumsq, (double)t);
    }
}
__global__ void scan_kernel() {
    const int CH = 79;
    __shared__ int part[256];
    int t = threadIdx.x, base = t * CH, s = 0;
    for (int i = 0; i < CH; i++) { int j = base + i; if (j < N_NODES) s += g_hist[j]; }
    part[t] = s; __syncthreads();
    for (int o = 1; o < 256; o <<= 1) {
        int v = (t >= o) ? part[t - o] : 0;
        __syncthreads(); part[t] += v; __syncthreads();
    }
    int run = (t > 0) ? part[t - 1] : 0;
    for (int i = 0; i < CH; i++) {
        int j = base + i;
        if (j < N_NODES) { g_off[j] = run; run += g_hist[j]; }
    }
    if (t == 255) g_off[N_NODES] = run;
}
__global__ void fill_kernel(const int* __restrict__ idx) {
    int i = blockIdx.x * blockDim.x + threadIdx.x;
    int st = gridDim.x * blockDim.x;
    for (int e = i; e < E_EDGES; e += st) {
        int n = idx[e];
        g_elist[g_off[n] + atomicAdd(&g_cursor[n], 1)] = e;
    }
}

// ---- tensor-core GEMM (mma.sync) -> g_msg. grid (X, 3) ----
__global__ void __launch_bounds__(512, 1)
gemm_kernel(const float* __restrict__ s, const float* __restrict__ r,
            const float* __restrict__ Wphi, const float* __restrict__ bphi,
            const float* __restrict__ Ww, const float* __restrict__ bw)
{
    extern __shared__ char sm[];
    __nv_bfloat16* A_hi = (__nv_bfloat16*)(sm + OFF_AHI);
    __nv_bfloat16* A_lo = (__nv_bfloat16*)(sm + OFF_ALO);
    __nv_bfloat16* B_hi = (__nv_bfloat16*)(sm + OFF_BHI);
    __nv_bfloat16* B_lo = (__nv_bfloat16*)(sm + OFF_BLO);
    float* Ww_s   = (float*)(sm + OFF_WW);
    float* bphi_s = (float*)(sm + OFF_BPHI);
    float* bw_s   = (float*)(sm + OFF_BW);
    float* rbf_s  = (float*)(sm + OFF_RBF);
    float* sp     = (float*)(sm + OFF_AHI);     // alias, pitch 132

    const int tid  = threadIdx.x;
    const int wid  = tid >> 5;
    const int lane = tid & 31;
    const int g    = lane >> 2;     // fragment group 0..7
    const int t4   = lane & 3;      // fragment thread 0..3
    const int mt   = wid >> 1;      // m-tile 0..7 (rows mt*16..+15)
    const int nh   = wid & 1;       // n-half (cols nh*64..+63)
    const int group = blockIdx.y;
    const int goff  = group * 128;

    // ---- one-time: weights to smem (B[n][k] hi/lo, pitch 136) ----
    for (int i = tid; i < 128 * 128; i += 512) {
        int n = i >> 7, k = i & 127;
        float x = Wphi[k * 384 + goff + n];
        __nv_bfloat16 h = __float2bfloat16(x);
        __nv_bfloat16 l = __float2bfloat16(x - __bfloat162float(h));
        B_hi[n * PITCH + k] = h;
        B_lo[n * PITCH + k] = l;
    }
    for (int i = tid; i < 20 * 128; i += 512)
        Ww_s[i] = Ww[(i >> 7) * 384 + goff + (i & 127)];
    if (tid < 128) { bphi_s[tid] = bphi[goff + tid]; bw_s[tid] = bw[goff + tid]; }
    __syncthreads();

    const int eL  = tid >> 2;           // staging: edge row
    const int cbL = (tid & 3) * 32;     // staging: col base
    const int e0  = mt * 16 + g;        // this thread's two edge rows
    const int e1  = e0 + 8;

    for (int tile = blockIdx.x; tile < NTILES; tile += gridDim.x) {
        const int ebase = tile * TILE_E;

        // 1) start s-tile loads (latency hidden by rbf + w-GEMM below)
        float4 st4[8];
        {
            const float* p = &s[(size_t)(ebase + eL) * 128 + cbL];
            #pragma unroll
            for (int q = 0; q < 8; q++) st4[q] = __ldg((const float4*)p + q);
        }

        // 2) rbf for this tile
        for (int i = tid; i < TILE_E * N_RBF; i += 512) {
            int el = i / N_RBF, n = i - el * N_RBF;
            float rx = __ldg(&r[(ebase + el) * 3]);
            float ry = __ldg(&r[(ebase + el) * 3 + 1]);
            float rz = __ldg(&r[(ebase + el) * 3 + 2]);
            float rn = sqrtf(rx * rx + ry * ry + rz * rz);
            float tt = sinf((float)(n + 1) * (3.14159265358979323846f / 5.0f) * rn) / rn;
            rbf_s[el * 21 + n] = (tt <= 5.0f)
                ? 0.5f * (cosf(3.14159265358979323846f * 0.2f * tt) + 1.0f) : 0.0f;
        }
        __syncthreads();   // rbf ready; prev-iter sp copy-out done (A region free)

        // 3) w = rbf @ Ww + bw (FFMA2) for this thread's 2 edges x 16 cols
        ull ww0[8], ww1[8];
        #pragma unroll
        for (int j = 0; j < 8; j++) {
            int cj = nh * 64 + j * 8 + t4 * 2;
            ww0[j] = *(ull*)&bw_s[cj];
            ww1[j] = ww0[j];
        }
        #pragma unroll 1
        for (int n = 0; n < N_RBF; n++) {
            float rb0 = rbf_s[e0 * 21 + n], rb1 = rbf_s[e1 * 21 + n];
            ull a0 = pack2(rb0, rb0), a1 = pack2(rb1, rb1);
            const float* q = &Ww_s[n * 128 + nh * 64 + t4 * 2];
            #pragma unroll
            for (int j = 0; j < 8; j++) {
                ull qq = *(ull*)(q + j * 8);
                ffma2(ww0[j], a0, qq);
                ffma2(ww1[j], a1, qq);
            }
        }

        // 4) convert staged s -> A_hi/A_lo smem
        #pragma unroll
        for (int b = 0; b < 4; b++) {
            uint4 hi, lo;
            split2(st4[2*b].x,   st4[2*b].y,   hi.x, lo.x);
            split2(st4[2*b].z,   st4[2*b].w,   hi.y, lo.y);
            split2(st4[2*b+1].x, st4[2*b+1].y, hi.z, lo.z);
            split2(st4[2*b+1].z, st4[2*b+1].w, hi.w, lo.w);
            int o = eL * PITCH + cbL + b * 8;
            *(uint4*)&A_hi[o] = hi;
            *(uint4*)&A_lo[o] = lo;
        }
        __syncthreads();   // A tiles ready

        // 5) MMA mainloop: 8 k-steps x 8 n-tiles x 3 precision terms
        float acc[8][4];
        #pragma unroll
        for (int j = 0; j < 8; j++)
            acc[j][0] = acc[j][1] = acc[j][2] = acc[j][3] = 0.f;

        #pragma unroll 1
        for (int kk = 0; kk < 8; kk++) {
            const int kb = kk * 16 + t4 * 2;
            const int ra = e0 * PITCH + kb;
            const int rb = e1 * PITCH + kb;
            uint32_t ah0 = *(uint32_t*)&A_hi[ra];
            uint32_t ah1 = *(uint32_t*)&A_hi[rb];
            uint32_t ah2 = *(uint32_t*)&A_hi[ra + 8];
            uint32_t ah3 = *(uint32_t*)&A_hi[rb + 8];
            uint32_t al0 = *(uint32_t*)&A_lo[ra];
            uint32_t al1 = *(uint32_t*)&A_lo[rb];
            uint32_t al2 = *(uint32_t*)&A_lo[ra + 8];
            uint32_t al3 = *(uint32_t*)&A_lo[rb + 8];
            #pragma unroll
            for (int j = 0; j < 8; j++) {
                int nrow = (nh * 64 + j * 8 + g) * PITCH + kk * 16 + t4 * 2;
                uint32_t bh0 = *(uint32_t*)&B_hi[nrow];
                uint32_t bh1 = *(uint32_t*)&B_hi[nrow + 8];
                uint32_t bl0 = *(uint32_t*)&B_lo[nrow];
                uint32_t bl1 = *(uint32_t*)&B_lo[nrow + 8];
                mma_bf16(acc[j], ah0, ah1, ah2, ah3, bh0, bh1);
                mma_bf16(acc[j], ah0, ah1, ah2, ah3, bl0, bl1);
                mma_bf16(acc[j], al0, al1, al2, al3, bh0, bh1);
            }
        }
        __syncthreads();   // all warps done reading A before sp overwrite

        // 6) sp = w * (acc + bphi) -> smem transpose buffer (pitch 132)
        #pragma unroll
        for (int j = 0; j < 8; j++) {
            int cj = nh * 64 + j * 8 + t4 * 2;
            ull bp = *(ull*)&bphi_s[cj];
            ull p0 = mul2(ww0[j], add2(pack2(acc[j][0], acc[j][1]), bp));
            ull p1 = mul2(ww1[j], add2(pack2(acc[j][2], acc[j][3]), bp));
            *(ull*)&sp[e0 * 132 + cj] = p0;
            *(ull*)&sp[e1 * 132 + cj] = p1;
        }
        __syncthreads();   // sp ready

        // 7) coalesced copy-out to g_msg
        #pragma unroll
        for (int kk = 0; kk < 8; kk++) {
            int i = kk * 512 + tid;
            int edge = i >> 5, ch = i & 31;
            float4 val = *(float4*)&sp[edge * 132 + ch * 4];
            *(float4*)&g_msg[(size_t)(ebase + edge) * 384 + goff + ch * 4] = val;
        }
    }
}

// ---- per-node gather ----
__global__ void __launch_bounds__(128)
gather_kernel(const float* __restrict__ r, const float* __restrict__ v,
              float* __restrict__ out)
{
    const int n = blockIdx.x;
    const int f = threadIdx.x;
    const float ginv = (float)(1.0 / sqrt(g_sumsq));
    const int beg = g_off[n], end = g_off[n + 1];

    float a0 = 0.f, a1 = 0.f, a2 = 0.f, as = 0.f;
    for (int p = beg; p < end; p++) {
        const int e = g_elist[p];
        const float* m  = &g_msg[(size_t)e * 384];
        const float* vp = &v[(size_t)e * 384];
        float sp0 = m[f], sp1 = m[128 + f], sp2 = m[256 + f];
        float r0 = __ldg(&r[e * 3]), r1 = __ldg(&r[e * 3 + 1]), r2 = __ldg(&r[e * 3 + 2]);
        a0 += sp2 * (r0 * ginv) + sp0 * vp[f];
        a1 += sp2 * (r1 * ginv) + sp0 * vp[128 + f];
        a2 += sp2 * (r2 * ginv) + sp0 * vp[256 + f];
        as += sp1;
    }
    size_t ob = (size_t)n * 384;
    out[ob + f]       = a0;
    out[ob + 128 + f] = a1;
    out[ob + 256 + f] = a2;
    out[OUT_S_OFF + (size_t)n * 128 + f] = as;
}

extern "C" void kernel_launch(void* const* d_in, const int* in_sizes, int n_in,
                              void* d_out, int out_size) {
    const float* s    = (const float*)d_in[0];
    const float* r    = (const float*)d_in[1];
    const float* v    = (const float*)d_in[2];
    const int*   idx  = (const int*)d_in[3];
    const float* Wphi = (const float*)d_in[4];
    const float* bphi = (const float*)d_in[5];
    const float* Ww   = (const float*)d_in[6];
    const float* bw   = (const float*)d_in[7];
    float* out = (float*)d_out;

    cudaFuncSetAttribute(gemm_kernel,
                         cudaFuncAttributeMaxDynamicSharedMemorySize, SMEM_SZ);
    gemm_kernel<<<dim3(148, 3), 512, SMEM_SZ>>>(s, r, Wphi, bphi, Ww, bw);

    reset_kernel<<<64, 256>>>();
    hist_sumsq_kernel<<<256, 256>>>(idx, r);
    scan_kernel<<<1, 256>>>();
    fill_kernel<<<256, 256>>>(idx);

    gather_kernel<<<N_NODES, 128>>>(r, v, out);
}